// round 15
// baseline (speedup 1.0000x reference)
#include <cuda_runtime.h>
#include <cuda_fp16.h>
#include <cstddef>
#include <cstdint>

// ---------------- problem constants ----------------
constexpr int kB = 8;
constexpr int kS = 512;
constexpr int kD = 512;
constexpr int kH = 8;
constexpr int kDK = 64;
constexpr int kL = 6;
constexpr int kF = 2048;
constexpr int kV = 32000;
constexpr int kNT = kB * kS;
constexpr float kNEG = -1e9f;
constexpr float kEPS = 1e-5f;
constexpr float kSCALE = 0.125f;

// ---------------- fp16 weight scratch layout (transposed to [N,K], hi only) -
constexpr size_t DD  = (size_t)kD * kD;
constexpr size_t DF  = (size_t)kD * kF;
constexpr size_t OFF_EA  = 0;
constexpr size_t OFF_DA  = OFF_EA  + 24 * DD;
constexpr size_t OFF_EW1 = OFF_DA  + 48 * DD;
constexpr size_t OFF_EW2 = OFF_EW1 + 6 * DF;
constexpr size_t OFF_DW1 = OFF_EW2 + 6 * DF;
constexpr size_t OFF_DW2 = OFF_DW1 + 6 * DF;
constexpr size_t OFF_FC  = OFF_DW2 + 6 * DF;
constexpr size_t W_TOTAL = OFF_FC + (size_t)kV * kD;

// ---------------- device scratch ----------------
__device__ float g_x[kNT * kD];
__device__ float g_y[kNT * kD];
__device__ float g_t[kNT * kD];
__device__ __half g_whi[W_TOTAL];
__device__ __half g_xhi[kNT * kD],  g_xlo[kNT * kD];
__device__ __half g_yhi[kNT * kD],  g_ylo[kNT * kD];
__device__ __half g_qhi[kNT * 3 * kD], g_qlo[kNT * 3 * kD];
__device__ __half g_chi[kNT * kD],  g_clo[kNT * kD];
__device__ __half g_fhi[(size_t)kNT * kF], g_flo[(size_t)kNT * kF];

// ========================= helpers ==========================================
__device__ __forceinline__ uint32_t smem_u32(const void* p) {
    uint32_t a;
    asm("{ .reg .u64 t; cvta.to.shared.u64 t, %1; cvt.u32.u64 %0, t; }"
        : "=r"(a) : "l"(p));
    return a;
}

__device__ __forceinline__ void ldsm_x4(uint32_t (&r)[4], uint32_t addr) {
    asm volatile("ldmatrix.sync.aligned.m8n8.x4.shared.b16 {%0,%1,%2,%3}, [%4];"
                 : "=r"(r[0]), "=r"(r[1]), "=r"(r[2]), "=r"(r[3]) : "r"(addr));
}
__device__ __forceinline__ void ldsm_x4_t(uint32_t (&r)[4], uint32_t addr) {
    asm volatile("ldmatrix.sync.aligned.m8n8.x4.trans.shared.b16 {%0,%1,%2,%3}, [%4];"
                 : "=r"(r[0]), "=r"(r[1]), "=r"(r[2]), "=r"(r[3]) : "r"(addr));
}

__device__ __forceinline__ void mma16816(float (&c)[4], const uint32_t (&a)[4],
                                         const uint32_t* b) {
    asm volatile(
        "mma.sync.aligned.m16n8k16.row.col.f32.f16.f16.f32 "
        "{%0,%1,%2,%3}, {%4,%5,%6,%7}, {%8,%9}, {%0,%1,%2,%3};"
        : "+f"(c[0]), "+f"(c[1]), "+f"(c[2]), "+f"(c[3])
        : "r"(a[0]), "r"(a[1]), "r"(a[2]), "r"(a[3]), "r"(b[0]), "r"(b[1]));
}

__device__ __forceinline__ uint32_t pk_h2(__half a, __half b) {
    __half2 t = __halves2half2(a, b);
    return *reinterpret_cast<uint32_t*>(&t);
}
__device__ __forceinline__ void split2(float a, float b, uint32_t& h, uint32_t& l) {
    __half ha = __float2half_rn(a), hb = __float2half_rn(b);
    h = pk_h2(ha, hb);
    l = pk_h2(__float2half_rn(a - __half2float(ha)),
              __float2half_rn(b - __half2float(hb)));
}

__device__ __forceinline__ void cp16(uint32_t dst, const void* src) {
    asm volatile("cp.async.cg.shared.global [%0], [%1], 16;" :: "r"(dst), "l"(src));
}
#define CP_COMMIT() asm volatile("cp.async.commit_group;")
template <int N>
__device__ __forceinline__ void cp_wait() {
    asm volatile("cp.async.wait_group %0;" :: "n"(N));
}

// ============== batched weight transpose + fp16 (hi only) ==================
__global__ __launch_bounds__(256)
void wconv_kernel(const float* __restrict__ W, __half* __restrict__ hi,
                  int K, int N) {
    const size_t moff = (size_t)blockIdx.z * K * N;
    W += moff; hi += moff;
    __shared__ float t[32][33];
    const int n0 = blockIdx.x << 5, k0 = blockIdx.y << 5;
    const int tx = threadIdx.x & 31, ty = threadIdx.x >> 5;
#pragma unroll
    for (int j = 0; j < 32; j += 8)
        t[ty + j][tx] = W[(size_t)(k0 + ty + j) * N + n0 + tx];
    __syncthreads();
#pragma unroll
    for (int j = 0; j < 32; j += 8)
        hi[(size_t)(n0 + ty + j) * K + k0 + tx] = __float2half_rn(t[tx][ty + j]);
}

// ======== HMMA GEMM (single-pass fp16): C = Ahi[M,K] * Bhi^T[N,K] + bias ====
// BK=64, NSTG=2, 256 threads (2x4 warps). Tiles: <64,128> or <128,256>.
constexpr int KP = 72;
constexpr int NSTG = 2;

template <int BM, int BN, bool RELU, bool F16OUT>
__global__ __launch_bounds__(256, (BN == 256) ? 1 : 2)
void hgemm_kernel(const __half* __restrict__ Ahi,
                  const __half* __restrict__ Bhi,
                  const float* __restrict__ bias,
                  float* __restrict__ C, __half* __restrict__ Chi,
                  __half* __restrict__ Clo,
                  int M, int N, int K, int ldc) {
    constexpr int WM  = BM / 2;               // warp m-extent
    constexpr int WN  = BN / 4;               // warp n-extent
    constexpr int MT  = WM / 16;
    constexpr int NT  = WN / 8;
    constexpr int SAB = BM * KP * 2;
    constexpr int SBB = BN * KP * 2;
    constexpr int STG = SAB + SBB;

    extern __shared__ char sm[];
    const int tid = threadIdx.x;
    const int lid = tid & 31, wid = tid >> 5;
    const int wm = wid >> 2, wn = wid & 3;
    const int bm = blockIdx.y * BM, bn = blockIdx.x * BN;
    const uint32_t smb = smem_u32(sm);

    const int nch = K >> 6;

    auto ISSUE = [&](int stage, int ck) {
        const uint32_t sb = smb + stage * STG;
        const int ko = ck * 64;
#pragma unroll
        for (int it = 0; it < BM / 32; it++) {
            int id = tid + (it << 8);
            int r = id >> 3, c8 = (id & 7) << 3;
            cp16(sb + (uint32_t)(r * KP + c8) * 2,
                 Ahi + (size_t)(bm + r) * K + ko + c8);
        }
#pragma unroll
        for (int it = 0; it < BN / 32; it++) {
            int id = tid + (it << 8);
            int r = id >> 3, c8 = (id & 7) << 3;
            cp16(sb + SAB + (uint32_t)(r * KP + c8) * 2,
                 Bhi + (size_t)(bn + r) * K + ko + c8);
        }
        CP_COMMIT();
    };

    float acc[MT][NT][4] = {};

    const int a_row = (lid & 7) + ((lid >> 3) & 1) * 8;
    const int a_kq = (lid >> 4) * 8;
    const int b_row = (lid & 7) + (lid >> 4) * 8;
    const int b_kq = ((lid >> 3) & 1) * 8;

    auto COMPUTE = [&](int s) {
        const uint32_t sA = smb + s * STG;
        const uint32_t sB = sA + SAB;
#pragma unroll
        for (int kk = 0; kk < 4; kk++) {
            uint32_t bh[NT / 2][4];
#pragma unroll
            for (int p = 0; p < NT / 2; p++) {
                uint32_t bd = sB + (uint32_t)(((wn * WN + p * 16 + b_row) * KP)
                                              + kk * 16 + b_kq) * 2;
                ldsm_x4(bh[p], bd);
            }
#pragma unroll
            for (int mt = 0; mt < MT; mt++) {
                uint32_t af[4];
                ldsm_x4(af, sA + (uint32_t)(((wm * WM + mt * 16 + a_row) * KP)
                                            + kk * 16 + a_kq) * 2);
#pragma unroll
                for (int nt = 0; nt < NT; nt++)
                    mma16816(acc[mt][nt], af, &bh[nt >> 1][(nt & 1) * 2]);
            }
        }
    };

    ISSUE(0, 0);
    for (int ch = 0; ch < nch; ch++) {
        cp_wait<0>();
        __syncthreads();
        if (ch + 1 < nch) ISSUE((ch + 1) & 1, ch + 1);
        COMPUTE(ch & 1);
    }

    const int er = bm + wm * WM + (lid >> 2);
    const int ec = bn + wn * WN + (lid & 3) * 2;
#pragma unroll
    for (int mt = 0; mt < MT; mt++)
#pragma unroll
        for (int nt = 0; nt < NT; nt++) {
            int r0 = er + mt * 16;
            int c0 = ec + (nt >> 1) * 16 + (nt & 1) * 8;
            float2 b2 = *(const float2*)(bias + c0);
            float v00 = acc[mt][nt][0] + b2.x, v01 = acc[mt][nt][1] + b2.y;
            float v10 = acc[mt][nt][2] + b2.x, v11 = acc[mt][nt][3] + b2.y;
            if (RELU) {
                v00 = fmaxf(v00, 0.f); v01 = fmaxf(v01, 0.f);
                v10 = fmaxf(v10, 0.f); v11 = fmaxf(v11, 0.f);
            }
            if (F16OUT) {
                uint32_t h0, l0, h1, l1;
                split2(v00, v01, h0, l0);
                split2(v10, v11, h1, l1);
                *(uint32_t*)(Chi + (size_t)r0 * ldc + c0) = h0;
                *(uint32_t*)(Clo + (size_t)r0 * ldc + c0) = l0;
                *(uint32_t*)(Chi + (size_t)(r0 + 8) * ldc + c0) = h1;
                *(uint32_t*)(Clo + (size_t)(r0 + 8) * ldc + c0) = l1;
            } else {
                *(float2*)(C + (size_t)r0 * ldc + c0) = make_float2(v00, v01);
                *(float2*)(C + (size_t)(r0 + 8) * ldc + c0) = make_float2(v10, v11);
            }
        }
}

constexpr int HG_SMEM_S = NSTG * (64 + 128) * KP * 2;    // 55296 (<64,128>)
constexpr int HG_SMEM_L = NSTG * (128 + 256) * KP * 2;   // 110592 (<128,256>)

// ============ fused flash attention (2-pass: Q full x K hi, P full x V hi) ==
constexpr int FAP = 72;
constexpr int FA_TILE = 64 * FAP;
constexpr int FA_SMEM = 4 * FA_TILE * 2 + 512 * 4;

__global__ __launch_bounds__(128)
void flash_kernel(const __half* __restrict__ QKVhi, const __half* __restrict__ QKVlo,
                  __half* __restrict__ Ohi, __half* __restrict__ Olo,
                  const int* __restrict__ qtok, const int* __restrict__ ktok,
                  int mode) {
    extern __shared__ char sm[];
    __half* sQh = (__half*)sm;
    __half* sQl = sQh + FA_TILE;
    __half* sKh = sQl + FA_TILE;
    __half* sVh = sKh + FA_TILE;
    float* maskf = (float*)(sVh + FA_TILE);

    const int tid = threadIdx.x, lid = tid & 31, w = tid >> 5;
    const int bh = blockIdx.y, b = bh >> 3, h = bh & 7;
    const int q0 = blockIdx.x << 6;
    const uint32_t smb = smem_u32(sm);
    const uint32_t QH_O = 0, QL_O = FA_TILE * 2, KH_O = 2 * FA_TILE * 2,
                   VH_O = 3 * FA_TILE * 2;

    if (mode == 0) {
        for (int i = tid; i < kS; i += 128)
            maskf[i] = (ktok[b * kS + i] != 0) ? 1.0f : 0.0f;
    }

    {
        const __half* Qh = QKVhi + (size_t)(b * kS + q0) * 1536 + h * kDK;
        const __half* Ql = QKVlo + (size_t)(b * kS + q0) * 1536 + h * kDK;
#pragma unroll
        for (int it = 0; it < 4; it++) {
            int i = tid + (it << 7);
            int r = i >> 3, c8 = (i & 7) << 3;
            *(uint4*)(sQh + r * FAP + c8) = *(const uint4*)(Qh + (size_t)r * 1536 + c8);
            *(uint4*)(sQl + r * FAP + c8) = *(const uint4*)(Ql + (size_t)r * 1536 + c8);
        }
    }

    float m0 = -1e30f, m1 = -1e30f, l0 = 0.f, l1 = 0.f;
    float o[8][4] = {};

    const int qg0 = q0 + w * 16 + (lid >> 2);
    const int qg1 = qg0 + 8;
    bool qv0 = true, qv1 = true;
    if (mode == 1) {
        qv0 = qtok[b * kS + qg0] != 0;
        qv1 = qtok[b * kS + qg1] != 0;
    }
    const int anyinv = __syncthreads_or(mode == 1 && (!qv0 || !qv1));
    const int ktmax = (mode == 1 && !anyinv) ? blockIdx.x : (kS / 64 - 1);

    const int a_row = (lid & 7) + ((lid >> 3) & 1) * 8;
    const int a_kq = (lid >> 4) * 8;
    const int b_row = (lid & 7) + (lid >> 4) * 8;
    const int b_kq = ((lid >> 3) & 1) * 8;
    const int v_row = (lid & 7) + ((lid >> 3) & 1) * 8;
    const int v_col8 = (lid >> 4) * 8;

    for (int kt = 0; kt <= ktmax; kt++) {
        const __half* Kh = QKVhi + (size_t)(b * kS + kt * 64) * 1536 + 512 + h * kDK;
        const __half* Vh = Kh + 512;
#pragma unroll
        for (int it = 0; it < 4; it++) {
            int i = tid + (it << 7);
            int r = i >> 3, c8 = (i & 7) << 3;
            size_t g = (size_t)r * 1536 + c8;
            uint32_t so = (uint32_t)(r * FAP + c8);
            *(uint4*)(sKh + so) = *(const uint4*)(Kh + g);
            *(uint4*)(sVh + so) = *(const uint4*)(Vh + g);
        }
        __syncthreads();

        float s[8][4] = {};
#pragma unroll
        for (int kk = 0; kk < 4; kk++) {
            uint32_t ah[4], al[4];
            uint32_t ad = smb + QH_O + (uint32_t)(((w * 16 + a_row) * FAP) + kk * 16 + a_kq) * 2;
            ldsm_x4(ah, ad);
            ldsm_x4(al, ad + (QL_O - QH_O));
#pragma unroll
            for (int p = 0; p < 4; p++) {
                uint32_t bf[4];
                uint32_t bd = smb + KH_O + (uint32_t)(((p * 16 + b_row) * FAP) + kk * 16 + b_kq) * 2;
                ldsm_x4(bf, bd);
                mma16816(s[p * 2 + 0], ah, &bf[0]);
                mma16816(s[p * 2 + 1], ah, &bf[2]);
            }
#pragma unroll
            for (int p = 0; p < 4; p++) {
                uint32_t bf[4];
                uint32_t bd = smb + KH_O + (uint32_t)(((p * 16 + b_row) * FAP) + kk * 16 + b_kq) * 2;
                ldsm_x4(bf, bd);
                mma16816(s[p * 2 + 0], al, &bf[0]);
                mma16816(s[p * 2 + 1], al, &bf[2]);
            }
        }

        float mx0 = -1e30f, mx1 = -1e30f;
#pragma unroll
        for (int j = 0; j < 8; j++) {
            int colb = 8 * j + 2 * (lid & 3);
#pragma unroll
            for (int e = 0; e < 4; e++) {
                int kg = kt * 64 + colb + (e & 1);
                float val = s[j][e] * kSCALE;
                if (mode == 0) {
                    val = (maskf[kg] != 0.0f) ? val : kNEG;
                } else {
                    bool qv = (e < 2) ? qv0 : qv1;
                    int qg = (e < 2) ? qg0 : qg1;
                    val = (qv && kg <= qg) ? val : kNEG;
                }
                s[j][e] = val;
                if (e < 2) mx0 = fmaxf(mx0, val);
                else       mx1 = fmaxf(mx1, val);
            }
        }
        mx0 = fmaxf(mx0, __shfl_xor_sync(0xffffffffu, mx0, 1));
        mx0 = fmaxf(mx0, __shfl_xor_sync(0xffffffffu, mx0, 2));
        mx1 = fmaxf(mx1, __shfl_xor_sync(0xffffffffu, mx1, 1));
        mx1 = fmaxf(mx1, __shfl_xor_sync(0xffffffffu, mx1, 2));

        float mn0 = fmaxf(m0, mx0), mn1 = fmaxf(m1, mx1);
        float al0 = __expf(m0 - mn0), al1 = __expf(m1 - mn1);
        m0 = mn0; m1 = mn1;

        float sum0 = 0.f, sum1 = 0.f;
#pragma unroll
        for (int j = 0; j < 8; j++) {
            s[j][0] = __expf(s[j][0] - mn0); sum0 += s[j][0];
            s[j][1] = __expf(s[j][1] - mn0); sum0 += s[j][1];
            s[j][2] = __expf(s[j][2] - mn1); sum1 += s[j][2];
            s[j][3] = __expf(s[j][3] - mn1); sum1 += s[j][3];
        }
        sum0 += __shfl_xor_sync(0xffffffffu, sum0, 1);
        sum0 += __shfl_xor_sync(0xffffffffu, sum0, 2);
        sum1 += __shfl_xor_sync(0xffffffffu, sum1, 1);
        sum1 += __shfl_xor_sync(0xffffffffu, sum1, 2);
        l0 = l0 * al0 + sum0;
        l1 = l1 * al1 + sum1;

#pragma unroll
        for (int j = 0; j < 8; j++) {
            o[j][0] *= al0; o[j][1] *= al0;
            o[j][2] *= al1; o[j][3] *= al1;
        }

#pragma unroll
        for (int kc = 0; kc < 4; kc++) {
            uint32_t pha[4], pla[4];
#pragma unroll
            for (int half16 = 0; half16 < 2; half16++) {
                int j = 2 * kc + half16;
                uint32_t h01, l01, h23, l23;
                split2(s[j][0], s[j][1], h01, l01);
                split2(s[j][2], s[j][3], h23, l23);
                pha[half16 * 2 + 0] = h01;
                pha[half16 * 2 + 1] = h23;
                pla[half16 * 2 + 0] = l01;
                pla[half16 * 2 + 1] = l23;
            }
#pragma unroll
            for (int dp = 0; dp < 4; dp++) {
                uint32_t vf[4];
                uint32_t vd = smb + VH_O + (uint32_t)(((kc * 16 + v_row) * FAP) + dp * 16 + v_col8) * 2;
                ldsm_x4_t(vf, vd);
                mma16816(o[dp * 2 + 0], pha, &vf[0]);
                mma16816(o[dp * 2 + 1], pha, &vf[2]);
            }
#pragma unroll
            for (int dp = 0; dp < 4; dp++) {
                uint32_t vf[4];
                uint32_t vd = smb + VH_O + (uint32_t)(((kc * 16 + v_row) * FAP) + dp * 16 + v_col8) * 2;
                ldsm_x4_t(vf, vd);
                mma16816(o[dp * 2 + 0], pla, &vf[0]);
                mma16816(o[dp * 2 + 1], pla, &vf[2]);
            }
        }
        __syncthreads();
    }

    const float inv0 = 1.0f / l0, inv1 = 1.0f / l1;
    const size_t row0 = (size_t)(b * kS + q0 + w * 16 + (lid >> 2)) * kD + h * kDK;
    const size_t row1 = row0 + 8 * kD;
#pragma unroll
    for (int j = 0; j < 8; j++) {
        int colb = 8 * j + 2 * (lid & 3);
        uint32_t h0, lo0, h1, lo1;
        split2(o[j][0] * inv0, o[j][1] * inv0, h0, lo0);
        split2(o[j][2] * inv1, o[j][3] * inv1, h1, lo1);
        *(uint32_t*)(Ohi + row0 + colb) = h0;
        *(uint32_t*)(Olo + row0 + colb) = lo0;
        *(uint32_t*)(Ohi + row1 + colb) = h1;
        *(uint32_t*)(Olo + row1 + colb) = lo1;
    }
}

// ---------------- embedding + PE, emits fp32 + hi/lo fp16 ----------------
__global__ void embed_kernel(const int* __restrict__ tok,
                             const float* __restrict__ emb,
                             const float* __restrict__ pos,
                             float* __restrict__ out,
                             __half* __restrict__ ohi, __half* __restrict__ olo) {
    int i = blockIdx.x * blockDim.x + threadIdx.x;
    int d = i & (kD - 1);
    int t = i >> 9;
    int s = t & (kS - 1);
    float v = emb[(size_t)tok[t] * kD + d] + pos[s * kD + d];
    out[i] = v;
    __half h = __float2half_rn(v);
    ohi[i] = h;
    olo[i] = __float2half_rn(v - __half2float(h));
}

// ---------------- x = LayerNorm(x + a), emits fp32 + hi/lo fp16 -------------
__global__ __launch_bounds__(128)
void add_ln_kernel(float* __restrict__ x, const float* __restrict__ a,
                   const float* __restrict__ g, const float* __restrict__ bet,
                   __half* __restrict__ xhi, __half* __restrict__ xlo) {
    const int r = blockIdx.x;
    const int tid = threadIdx.x;
    __shared__ float red[4];

    float v[4];
#pragma unroll
    for (int i = 0; i < 4; i++) {
        int c = tid + (i << 7);
        size_t idx = (size_t)r * kD + c;
        v[i] = x[idx] + a[idx];
    }

    float s = v[0] + v[1] + v[2] + v[3];
    for (int o = 16; o; o >>= 1) s += __shfl_xor_sync(0xffffffffu, s, o);
    if ((tid & 31) == 0) red[tid >> 5] = s;
    __syncthreads();
    s = red[0] + red[1] + red[2] + red[3];
    __syncthreads();
    const float mu = s * (1.0f / kD);

    float sq = 0.0f;
#pragma unroll
    for (int i = 0; i < 4; i++) { float d = v[i] - mu; sq += d * d; }
    for (int o = 16; o; o >>= 1) sq += __shfl_xor_sync(0xffffffffu, sq, o);
    if ((tid & 31) == 0) red[tid >> 5] = sq;
    __syncthreads();
    sq = red[0] + red[1] + red[2] + red[3];
    const float rstd = rsqrtf(sq * (1.0f / kD) + kEPS);

#pragma unroll
    for (int i = 0; i < 4; i++) {
        int c = tid + (i << 7);
        size_t idx = (size_t)r * kD + c;
        float o = (v[i] - mu) * rstd * g[c] + bet[c];
        x[idx] = o;
        __half h = __float2half_rn(o);
        xhi[idx] = h;
        xlo[idx] = __float2half_rn(o - __half2float(h));
    }
}

// ---------------- host-side orchestration ----------------------------------
static void hgemm(const __half* ahi, const __half* bhi,
                  const float* bias, float* C, __half* Chi, __half* Clo,
                  int M, int N, int K, int ldc, bool relu) {
    const bool f16 = (Chi != nullptr);
    if (N == 512) {
        dim3 grid(N / 128, M / 64);
        if (f16) {
            if (relu) hgemm_kernel<64, 128, true,  true><<<grid, 256, HG_SMEM_S>>>(ahi, bhi, bias, C, Chi, Clo, M, N, K, ldc);
            else      hgemm_kernel<64, 128, false, true><<<grid, 256, HG_SMEM_S>>>(ahi, bhi, bias, C, Chi, Clo, M, N, K, ldc);
        } else {
            if (relu) hgemm_kernel<64, 128, true,  false><<<grid, 256, HG_SMEM_S>>>(ahi, bhi, bias, C, Chi, Clo, M, N, K, ldc);
            else      hgemm_kernel<64, 128, false, false><<<grid, 256, HG_SMEM_S>>>(ahi, bhi, bias, C, Chi, Clo, M, N, K, ldc);
        }
    } else {
        dim3 grid(N / 256, M / 128);
        if (f16) {
            if (relu) hgemm_kernel<128, 256, true,  true><<<grid, 256, HG_SMEM_L>>>(ahi, bhi, bias, C, Chi, Clo, M, N, K, ldc);
            else      hgemm_kernel<128, 256, false, true><<<grid, 256, HG_SMEM_L>>>(ahi, bhi, bias, C, Chi, Clo, M, N, K, ldc);
        } else {
            if (relu) hgemm_kernel<128, 256, true,  false><<<grid, 256, HG_SMEM_L>>>(ahi, bhi, bias, C, Chi, Clo, M, N, K, ldc);
            else      hgemm_kernel<128, 256, false, false><<<grid, 256, HG_SMEM_L>>>(ahi, bhi, bias, C, Chi, Clo, M, N, K, ldc);
        }
    }
}

extern "C" void kernel_launch(void* const* d_in, const int* in_sizes, int n_in,
                              void* d_out, int out_size) {
    const int*   src     = (const int*)d_in[0];
    const int*   tgt     = (const int*)d_in[1];
    const float* enc_emb = (const float*)d_in[2];
    const float* dec_emb = (const float*)d_in[3];
    const float* pos     = (const float*)d_in[4];
    const float* enc_aw  = (const float*)d_in[5];
    const float* enc_ab  = (const float*)d_in[6];
    const float* enc_w1  = (const float*)d_in[7];
    const float* enc_b1  = (const float*)d_in[8];
    const float* enc_w2  = (const float*)d_in[9];
    const float* enc_b2  = (const float*)d_in[10];
    const float* enc_lng = (const float*)d_in[11];
    const float* enc_lnb = (const float*)d_in[12];
    const float* dec_aw  = (const float*)d_in[13];
    const float* dec_ab  = (const float*)d_in[14];
    const float* dec_w1  = (const float*)d_in[15];
    const float* dec_b1  = (const float*)d_in[16];
    const float* dec_w2  = (const float*)d_in[17];
    const float* dec_b2  = (const float*)d_in[18];
    const float* dec_lng = (const float*)d_in[19];
    const float* dec_lnb = (const float*)d_in[20];
    const float* fc_w    = (const float*)d_in[21];
    const float* fc_b    = (const float*)d_in[22];

    float *x, *y, *t;
    __half *whi, *xhi, *xlo, *yhi, *ylo, *qhi, *qlo, *chi, *clo, *fhi, *flo;
    cudaGetSymbolAddress((void**)&x,   g_x);
    cudaGetSymbolAddress((void**)&y,   g_y);
    cudaGetSymbolAddress((void**)&t,   g_t);
    cudaGetSymbolAddress((void**)&whi, g_whi);
    cudaGetSymbolAddress((void**)&xhi, g_xhi);
    cudaGetSymbolAddress((void**)&xlo, g_xlo);
    cudaGetSymbolAddress((void**)&yhi, g_yhi);
    cudaGetSymbolAddress((void**)&ylo, g_ylo);
    cudaGetSymbolAddress((void**)&qhi, g_qhi);
    cudaGetSymbolAddress((void**)&qlo, g_qlo);
    cudaGetSymbolAddress((void**)&chi, g_chi);
    cudaGetSymbolAddress((void**)&clo, g_clo);
    cudaGetSymbolAddress((void**)&fhi, g_fhi);
    cudaGetSymbolAddress((void**)&flo, g_flo);

    cudaFuncSetAttribute(hgemm_kernel<64, 128, false, false>, cudaFuncAttributeMaxDynamicSharedMemorySize, HG_SMEM_S);
    cudaFuncSetAttribute(hgemm_kernel<64, 128, true,  false>, cudaFuncAttributeMaxDynamicSharedMemorySize, HG_SMEM_S);
    cudaFuncSetAttribute(hgemm_kernel<64, 128, false, true>,  cudaFuncAttributeMaxDynamicSharedMemorySize, HG_SMEM_S);
    cudaFuncSetAttribute(hgemm_kernel<64, 128, true,  true>,  cudaFuncAttributeMaxDynamicSharedMemorySize, HG_SMEM_S);
    cudaFuncSetAttribute(hgemm_kernel<128, 256, false, false>, cudaFuncAttributeMaxDynamicSharedMemorySize, HG_SMEM_L);
    cudaFuncSetAttribute(hgemm_kernel<128, 256, true,  false>, cudaFuncAttributeMaxDynamicSharedMemorySize, HG_SMEM_L);
    cudaFuncSetAttribute(hgemm_kernel<128, 256, false, true>,  cudaFuncAttributeMaxDynamicSharedMemorySize, HG_SMEM_L);
    cudaFuncSetAttribute(hgemm_kernel<128, 256, true,  true>,  cudaFuncAttributeMaxDynamicSharedMemorySize, HG_SMEM_L);
    cudaFuncSetAttribute(flash_kernel, cudaFuncAttributeMaxDynamicSharedMemorySize, FA_SMEM);

    const int embBlocks = (kNT * kD) / 256;

    // keep first QKV hgemm at MY launch index 3 (ncu -s 5 alignment)
    wconv_kernel<<<dim3(16, 16, 24), 256>>>(enc_aw, whi + OFF_EA, kD, kD);
    embed_kernel<<<embBlocks, 256>>>(src, enc_emb, pos, x, xhi, xlo);
    wconv_kernel<<<dim3(64, 16, 6),  256>>>(enc_w1, whi + OFF_EW1, kD, kF);
    hgemm(xhi, whi + OFF_EA, enc_ab, nullptr, qhi, qlo, kNT, 3 * kD, kD, 3 * kD, false);
    wconv_kernel<<<dim3(16, 64, 6),  256>>>(enc_w2, whi + OFF_EW2, kF, kD);

    // ---------------- encoder ----------------
    for (int l = 0; l < kL; l++) {
        const __half* wh = whi + OFF_EA + (size_t)l * 4 * DD;
        const float* Wb = enc_ab + (size_t)l * 4 * kD;
        if (l > 0)
            hgemm(xhi, wh, Wb, nullptr, qhi, qlo, kNT, 3 * kD, kD, 3 * kD, false);
        flash_kernel<<<dim3(kS / 64, kB * kH), 128, FA_SMEM>>>(qhi, qlo, chi, clo, nullptr, src, 0);
        hgemm(chi, wh + 3 * DD, Wb + 3 * kD, t, nullptr, nullptr, kNT, kD, kD, kD, false);
        add_ln_kernel<<<kNT, 128>>>(x, t, enc_lng + (size_t)(l * 2 + 0) * kD,
                                    enc_lnb + (size_t)(l * 2 + 0) * kD, xhi, xlo);
        hgemm(xhi, whi + OFF_EW1 + (size_t)l * DF, enc_b1 + (size_t)l * kF,
              nullptr, fhi, flo, kNT, kF, kD, kF, true);
        hgemm(fhi, whi + OFF_EW2 + (size_t)l * DF, enc_b2 + (size_t)l * kD,
              t, nullptr, nullptr, kNT, kD, kF, kD, false);
        add_ln_kernel<<<kNT, 128>>>(x, t, enc_lng + (size_t)(l * 2 + 1) * kD,
                                    enc_lnb + (size_t)(l * 2 + 1) * kD, xhi, xlo);
    }
    // xhi holds enc_out (decoder never overwrites)

    wconv_kernel<<<dim3(16, 16, 48), 256>>>(dec_aw, whi + OFF_DA, kD, kD);
    wconv_kernel<<<dim3(64, 16, 6), 256>>>(dec_w1, whi + OFF_DW1, kD, kF);
    wconv_kernel<<<dim3(16, 64, 6), 256>>>(dec_w2, whi + OFF_DW2, kF, kD);
    wconv_kernel<<<dim3(1000, 16, 1), 256>>>(fc_w, whi + OFF_FC, kD, kV);
    embed_kernel<<<embBlocks, 256>>>(tgt, dec_emb, pos, y, yhi, ylo);

    // ---------------- decoder ----------------
    for (int l = 0; l < kL; l++) {
        const __half* wh = whi + OFF_DA + (size_t)l * 8 * DD;
        const float* Wb = dec_ab + (size_t)l * 8 * kD;
        // self-attention
        hgemm(yhi, wh, Wb, nullptr, qhi, qlo, kNT, 3 * kD, kD, 3 * kD, false);
        flash_kernel<<<dim3(kS / 64, kB * kH), 128, FA_SMEM>>>(qhi, qlo, chi, clo, tgt, tgt, 1);
        hgemm(chi, wh + 3 * DD, Wb + 3 * kD, t, nullptr, nullptr, kNT, kD, kD, kD, false);
        add_ln_kernel<<<kNT, 128>>>(y, t, dec_lng + (size_t)(l * 3 + 0) * kD,
                                    dec_lnb + (size_t)(l * 3 + 0) * kD, yhi, ylo);
        // cross-attention: Q from y, KV from enc_out (xhi)
        hgemm(yhi, wh + 4 * DD, Wb + 4 * kD, nullptr, qhi, qlo, kNT, kD, kD, 3 * kD, false);
        hgemm(xhi, wh + 5 * DD, Wb + 5 * kD, nullptr, qhi + kD, qlo + kD,
              kNT, 2 * kD, kD, 3 * kD, false);
        flash_kernel<<<dim3(kS / 64, kB * kH), 128, FA_SMEM>>>(qhi, qlo, chi, clo, nullptr, src, 0);
        hgemm(chi, wh + 7 * DD, Wb + 7 * kD, t, nullptr, nullptr, kNT, kD, kD, kD, false);
        add_ln_kernel<<<kNT, 128>>>(y, t, dec_lng + (size_t)(l * 3 + 1) * kD,
                                    dec_lnb + (size_t)(l * 3 + 1) * kD, yhi, ylo);
        // FFN
        hgemm(yhi, whi + OFF_DW1 + (size_t)l * DF, dec_b1 + (size_t)l * kF,
              nullptr, fhi, flo, kNT, kF, kD, kF, true);
        hgemm(fhi, whi + OFF_DW2 + (size_t)l * DF, dec_b2 + (size_t)l * kD,
              t, nullptr, nullptr, kNT, kD, kF, kD, false);
        add_ln_kernel<<<kNT, 128>>>(y, t, dec_lng + (size_t)(l * 3 + 2) * kD,
                                    dec_lnb + (size_t)(l * 3 + 2) * kD, yhi, ylo);
    }

    // ---------------- final projection to vocab ----------------
    hgemm(yhi, whi + OFF_FC, fc_b, (float*)d_out, nullptr, nullptr,
          kNT, kV, kD, kV, false);
}

// round 16
// speedup vs baseline: 1.1976x; 1.1976x over previous
#include <cuda_runtime.h>
#include <cuda_fp16.h>
#include <cstddef>
#include <cstdint>

// ---------------- problem constants ----------------
constexpr int kB = 8;
constexpr int kS = 512;
constexpr int kD = 512;
constexpr int kH = 8;
constexpr int kDK = 64;
constexpr int kL = 6;
constexpr int kF = 2048;
constexpr int kV = 32000;
constexpr int kNT = kB * kS;
constexpr float kNEG = -1e9f;
constexpr float kEPS = 1e-5f;
constexpr float kSCALE = 0.125f;

// ---------------- fp16 weight scratch layout (transposed to [N,K]) ---------
constexpr size_t DD  = (size_t)kD * kD;
constexpr size_t DF  = (size_t)kD * kF;
constexpr size_t OFF_EA  = 0;
constexpr size_t OFF_DA  = OFF_EA  + 24 * DD;
constexpr size_t OFF_EW1 = OFF_DA  + 48 * DD;
constexpr size_t OFF_EW2 = OFF_EW1 + 6 * DF;
constexpr size_t OFF_DW1 = OFF_EW2 + 6 * DF;
constexpr size_t OFF_DW2 = OFF_DW1 + 6 * DF;
constexpr size_t OFF_FC  = OFF_DW2 + 6 * DF;
constexpr size_t W_TOTAL = OFF_FC + (size_t)kV * kD;

// ---------------- device scratch (hi-only fp16 everywhere) ----------------
__device__ float g_x[kNT * kD];
__device__ float g_y[kNT * kD];
__device__ float g_t[kNT * kD];
__device__ __half g_whi[W_TOTAL];
__device__ __half g_xhi[kNT * kD];
__device__ __half g_yhi[kNT * kD];
__device__ __half g_qhi[kNT * 3 * kD];
__device__ __half g_chi[kNT * kD];
__device__ __half g_fhi[(size_t)kNT * kF];

// ========================= helpers ==========================================
__device__ __forceinline__ uint32_t smem_u32(const void* p) {
    uint32_t a;
    asm("{ .reg .u64 t; cvta.to.shared.u64 t, %1; cvt.u32.u64 %0, t; }"
        : "=r"(a) : "l"(p));
    return a;
}

__device__ __forceinline__ void ldsm_x4(uint32_t (&r)[4], uint32_t addr) {
    asm volatile("ldmatrix.sync.aligned.m8n8.x4.shared.b16 {%0,%1,%2,%3}, [%4];"
                 : "=r"(r[0]), "=r"(r[1]), "=r"(r[2]), "=r"(r[3]) : "r"(addr));
}
__device__ __forceinline__ void ldsm_x4_t(uint32_t (&r)[4], uint32_t addr) {
    asm volatile("ldmatrix.sync.aligned.m8n8.x4.trans.shared.b16 {%0,%1,%2,%3}, [%4];"
                 : "=r"(r[0]), "=r"(r[1]), "=r"(r[2]), "=r"(r[3]) : "r"(addr));
}

__device__ __forceinline__ void mma16816(float (&c)[4], const uint32_t (&a)[4],
                                         const uint32_t* b) {
    asm volatile(
        "mma.sync.aligned.m16n8k16.row.col.f32.f16.f16.f32 "
        "{%0,%1,%2,%3}, {%4,%5,%6,%7}, {%8,%9}, {%0,%1,%2,%3};"
        : "+f"(c[0]), "+f"(c[1]), "+f"(c[2]), "+f"(c[3])
        : "r"(a[0]), "r"(a[1]), "r"(a[2]), "r"(a[3]), "r"(b[0]), "r"(b[1]));
}

__device__ __forceinline__ uint32_t pk_h2(__half a, __half b) {
    __half2 t = __halves2half2(a, b);
    return *reinterpret_cast<uint32_t*>(&t);
}
__device__ __forceinline__ uint32_t cvt_h2(float a, float b) {
    __half2 t = __floats2half2_rn(a, b);
    return *reinterpret_cast<uint32_t*>(&t);
}

__device__ __forceinline__ void cp16(uint32_t dst, const void* src) {
    asm volatile("cp.async.cg.shared.global [%0], [%1], 16;" :: "r"(dst), "l"(src));
}
#define CP_COMMIT() asm volatile("cp.async.commit_group;")
template <int N>
__device__ __forceinline__ void cp_wait() {
    asm volatile("cp.async.wait_group %0;" :: "n"(N));
}

// ============== batched weight transpose + fp16 (hi only) ==================
__global__ __launch_bounds__(256)
void wconv_kernel(const float* __restrict__ W, __half* __restrict__ hi,
                  int K, int N) {
    const size_t moff = (size_t)blockIdx.z * K * N;
    W += moff; hi += moff;
    __shared__ float t[32][33];
    const int n0 = blockIdx.x << 5, k0 = blockIdx.y << 5;
    const int tx = threadIdx.x & 31, ty = threadIdx.x >> 5;
#pragma unroll
    for (int j = 0; j < 32; j += 8)
        t[ty + j][tx] = W[(size_t)(k0 + ty + j) * N + n0 + tx];
    __syncthreads();
#pragma unroll
    for (int j = 0; j < 32; j += 8)
        hi[(size_t)(n0 + ty + j) * K + k0 + tx] = __float2half_rn(t[tx][ty + j]);
}

// ======== HMMA GEMM (single-pass fp16): C = Ahi[M,K] * Bhi^T[N,K] + bias ====
// Round-11 config: BK=64, NSTG=2, 256 threads (2x4 warps), 2 CTAs/SM.
constexpr int KP = 72;
constexpr int NSTG = 2;

template <int BM, bool RELU, bool F16OUT>
__global__ __launch_bounds__(256, 2)
void hgemm_kernel(const __half* __restrict__ Ahi,
                  const __half* __restrict__ Bhi,
                  const float* __restrict__ bias,
                  float* __restrict__ C, __half* __restrict__ Chi,
                  int M, int N, int K, int ldc) {
    constexpr int WM  = BM / 2;
    constexpr int MT  = WM / 16;
    constexpr int SAB = BM * KP * 2;
    constexpr int SBB = 128 * KP * 2;
    constexpr int STG = SAB + SBB;

    extern __shared__ char sm[];
    const int tid = threadIdx.x;
    const int lid = tid & 31, wid = tid >> 5;
    const int wm = wid >> 2, wn = wid & 3;
    const int bm = blockIdx.y * BM, bn = blockIdx.x << 7;
    const uint32_t smb = smem_u32(sm);

    const int nch = K >> 6;

    auto ISSUE = [&](int stage, int ck) {
        const uint32_t sb = smb + stage * STG;
        const int ko = ck * 64;
#pragma unroll
        for (int it = 0; it < BM / 32; it++) {
            int id = tid + (it << 8);
            int r = id >> 3, c8 = (id & 7) << 3;
            cp16(sb + (uint32_t)(r * KP + c8) * 2,
                 Ahi + (size_t)(bm + r) * K + ko + c8);
        }
#pragma unroll
        for (int it = 0; it < 4; it++) {
            int id = tid + (it << 8);
            int r = id >> 3, c8 = (id & 7) << 3;
            cp16(sb + SAB + (uint32_t)(r * KP + c8) * 2,
                 Bhi + (size_t)(bn + r) * K + ko + c8);
        }
        CP_COMMIT();
    };

    float acc[MT][4][4] = {};

    const int a_row = (lid & 7) + ((lid >> 3) & 1) * 8;
    const int a_kq = (lid >> 4) * 8;
    const int b_row = (lid & 7) + (lid >> 4) * 8;
    const int b_kq = ((lid >> 3) & 1) * 8;

    auto COMPUTE = [&](int s) {
        const uint32_t sA = smb + s * STG;
        const uint32_t sB = sA + SAB;
#pragma unroll
        for (int kk = 0; kk < 4; kk++) {
            uint32_t bh[2][4];
#pragma unroll
            for (int p = 0; p < 2; p++) {
                uint32_t bd = sB + (uint32_t)(((wn * 32 + p * 16 + b_row) * KP)
                                              + kk * 16 + b_kq) * 2;
                ldsm_x4(bh[p], bd);
            }
#pragma unroll
            for (int mt = 0; mt < MT; mt++) {
                uint32_t af[4];
                ldsm_x4(af, sA + (uint32_t)(((wm * WM + mt * 16 + a_row) * KP)
                                            + kk * 16 + a_kq) * 2);
#pragma unroll
                for (int nt = 0; nt < 4; nt++)
                    mma16816(acc[mt][nt], af, &bh[nt >> 1][(nt & 1) * 2]);
            }
        }
    };

    ISSUE(0, 0);
    for (int ch = 0; ch < nch; ch++) {
        cp_wait<0>();
        __syncthreads();
        if (ch + 1 < nch) ISSUE((ch + 1) & 1, ch + 1);
        COMPUTE(ch & 1);
    }

    const int er = bm + wm * WM + (lid >> 2);
    const int ec = bn + wn * 32 + (lid & 3) * 2;
#pragma unroll
    for (int mt = 0; mt < MT; mt++)
#pragma unroll
        for (int nt = 0; nt < 4; nt++) {
            int r0 = er + mt * 16, c0 = ec + nt * 8;
            float2 b2 = *(const float2*)(bias + c0);
            float v00 = acc[mt][nt][0] + b2.x, v01 = acc[mt][nt][1] + b2.y;
            float v10 = acc[mt][nt][2] + b2.x, v11 = acc[mt][nt][3] + b2.y;
            if (RELU) {
                v00 = fmaxf(v00, 0.f); v01 = fmaxf(v01, 0.f);
                v10 = fmaxf(v10, 0.f); v11 = fmaxf(v11, 0.f);
            }
            if (F16OUT) {
                *(uint32_t*)(Chi + (size_t)r0 * ldc + c0) = cvt_h2(v00, v01);
                *(uint32_t*)(Chi + (size_t)(r0 + 8) * ldc + c0) = cvt_h2(v10, v11);
            } else {
                *(float2*)(C + (size_t)r0 * ldc + c0) = make_float2(v00, v01);
                *(float2*)(C + (size_t)(r0 + 8) * ldc + c0) = make_float2(v10, v11);
            }
        }
}

constexpr int HG_SMEM128 = NSTG * (128 + 128) * KP * 2;   // 73728
constexpr int HG_SMEM64  = NSTG * (64 + 128) * KP * 2;    // 55296

// ============ fused flash attention (single-pass fp16) ======================
constexpr int FAP = 72;
constexpr int FA_TILE = 64 * FAP;
constexpr int FA_SMEM = 3 * FA_TILE * 2 + 512 * 4;        // Q, K, V hi + mask

__global__ __launch_bounds__(128)
void flash_kernel(const __half* __restrict__ QKVhi,
                  __half* __restrict__ Ohi,
                  const int* __restrict__ qtok, const int* __restrict__ ktok,
                  int mode) {
    extern __shared__ char sm[];
    __half* sQh = (__half*)sm;
    __half* sKh = sQh + FA_TILE;
    __half* sVh = sKh + FA_TILE;
    float* maskf = (float*)(sVh + FA_TILE);

    const int tid = threadIdx.x, lid = tid & 31, w = tid >> 5;
    const int bh = blockIdx.y, b = bh >> 3, h = bh & 7;
    const int q0 = blockIdx.x << 6;
    const uint32_t smb = smem_u32(sm);
    const uint32_t QH_O = 0, KH_O = FA_TILE * 2, VH_O = 2 * FA_TILE * 2;

    if (mode == 0) {
        for (int i = tid; i < kS; i += 128)
            maskf[i] = (ktok[b * kS + i] != 0) ? 1.0f : 0.0f;
    }

    {
        const __half* Qh = QKVhi + (size_t)(b * kS + q0) * 1536 + h * kDK;
#pragma unroll
        for (int it = 0; it < 4; it++) {
            int i = tid + (it << 7);
            int r = i >> 3, c8 = (i & 7) << 3;
            *(uint4*)(sQh + r * FAP + c8) = *(const uint4*)(Qh + (size_t)r * 1536 + c8);
        }
    }

    float m0 = -1e30f, m1 = -1e30f, l0 = 0.f, l1 = 0.f;
    float o[8][4] = {};

    const int qg0 = q0 + w * 16 + (lid >> 2);
    const int qg1 = qg0 + 8;
    bool qv0 = true, qv1 = true;
    if (mode == 1) {
        qv0 = qtok[b * kS + qg0] != 0;
        qv1 = qtok[b * kS + qg1] != 0;
    }
    const int anyinv = __syncthreads_or(mode == 1 && (!qv0 || !qv1));
    const int ktmax = (mode == 1 && !anyinv) ? blockIdx.x : (kS / 64 - 1);

    const int a_row = (lid & 7) + ((lid >> 3) & 1) * 8;
    const int a_kq = (lid >> 4) * 8;
    const int b_row = (lid & 7) + (lid >> 4) * 8;
    const int b_kq = ((lid >> 3) & 1) * 8;
    const int v_row = (lid & 7) + ((lid >> 3) & 1) * 8;
    const int v_col8 = (lid >> 4) * 8;

    for (int kt = 0; kt <= ktmax; kt++) {
        const __half* Kh = QKVhi + (size_t)(b * kS + kt * 64) * 1536 + 512 + h * kDK;
        const __half* Vh = Kh + 512;
#pragma unroll
        for (int it = 0; it < 4; it++) {
            int i = tid + (it << 7);
            int r = i >> 3, c8 = (i & 7) << 3;
            size_t g = (size_t)r * 1536 + c8;
            uint32_t so = (uint32_t)(r * FAP + c8);
            *(uint4*)(sKh + so) = *(const uint4*)(Kh + g);
            *(uint4*)(sVh + so) = *(const uint4*)(Vh + g);
        }
        __syncthreads();

        // ---- S = Qhi Khi^T ----
        float s[8][4] = {};
#pragma unroll
        for (int kk = 0; kk < 4; kk++) {
            uint32_t ah[4];
            ldsm_x4(ah, smb + QH_O +
                    (uint32_t)(((w * 16 + a_row) * FAP) + kk * 16 + a_kq) * 2);
#pragma unroll
            for (int p = 0; p < 4; p++) {
                uint32_t bf[4];
                uint32_t bd = smb + KH_O + (uint32_t)(((p * 16 + b_row) * FAP) + kk * 16 + b_kq) * 2;
                ldsm_x4(bf, bd);
                mma16816(s[p * 2 + 0], ah, &bf[0]);
                mma16816(s[p * 2 + 1], ah, &bf[2]);
            }
        }

        float mx0 = -1e30f, mx1 = -1e30f;
#pragma unroll
        for (int j = 0; j < 8; j++) {
            int colb = 8 * j + 2 * (lid & 3);
#pragma unroll
            for (int e = 0; e < 4; e++) {
                int kg = kt * 64 + colb + (e & 1);
                float val = s[j][e] * kSCALE;
                if (mode == 0) {
                    val = (maskf[kg] != 0.0f) ? val : kNEG;
                } else {
                    bool qv = (e < 2) ? qv0 : qv1;
                    int qg = (e < 2) ? qg0 : qg1;
                    val = (qv && kg <= qg) ? val : kNEG;
                }
                s[j][e] = val;
                if (e < 2) mx0 = fmaxf(mx0, val);
                else       mx1 = fmaxf(mx1, val);
            }
        }
        mx0 = fmaxf(mx0, __shfl_xor_sync(0xffffffffu, mx0, 1));
        mx0 = fmaxf(mx0, __shfl_xor_sync(0xffffffffu, mx0, 2));
        mx1 = fmaxf(mx1, __shfl_xor_sync(0xffffffffu, mx1, 1));
        mx1 = fmaxf(mx1, __shfl_xor_sync(0xffffffffu, mx1, 2));

        float mn0 = fmaxf(m0, mx0), mn1 = fmaxf(m1, mx1);
        float al0 = __expf(m0 - mn0), al1 = __expf(m1 - mn1);
        m0 = mn0; m1 = mn1;

        float sum0 = 0.f, sum1 = 0.f;
#pragma unroll
        for (int j = 0; j < 8; j++) {
            s[j][0] = __expf(s[j][0] - mn0); sum0 += s[j][0];
            s[j][1] = __expf(s[j][1] - mn0); sum0 += s[j][1];
            s[j][2] = __expf(s[j][2] - mn1); sum1 += s[j][2];
            s[j][3] = __expf(s[j][3] - mn1); sum1 += s[j][3];
        }
        sum0 += __shfl_xor_sync(0xffffffffu, sum0, 1);
        sum0 += __shfl_xor_sync(0xffffffffu, sum0, 2);
        sum1 += __shfl_xor_sync(0xffffffffu, sum1, 1);
        sum1 += __shfl_xor_sync(0xffffffffu, sum1, 2);
        l0 = l0 * al0 + sum0;
        l1 = l1 * al1 + sum1;

#pragma unroll
        for (int j = 0; j < 8; j++) {
            o[j][0] *= al0; o[j][1] *= al0;
            o[j][2] *= al1; o[j][3] *= al1;
        }

        // ---- O += Phi Vhi ----
#pragma unroll
        for (int kc = 0; kc < 4; kc++) {
            uint32_t pha[4];
#pragma unroll
            for (int half16 = 0; half16 < 2; half16++) {
                int j = 2 * kc + half16;
                pha[half16 * 2 + 0] = cvt_h2(s[j][0], s[j][1]);
                pha[half16 * 2 + 1] = cvt_h2(s[j][2], s[j][3]);
            }
#pragma unroll
            for (int dp = 0; dp < 4; dp++) {
                uint32_t vf[4];
                uint32_t vd = smb + VH_O + (uint32_t)(((kc * 16 + v_row) * FAP) + dp * 16 + v_col8) * 2;
                ldsm_x4_t(vf, vd);
                mma16816(o[dp * 2 + 0], pha, &vf[0]);
                mma16816(o[dp * 2 + 1], pha, &vf[2]);
            }
        }
        __syncthreads();
    }

    const float inv0 = 1.0f / l0, inv1 = 1.0f / l1;
    const size_t row0 = (size_t)(b * kS + q0 + w * 16 + (lid >> 2)) * kD + h * kDK;
    const size_t row1 = row0 + 8 * kD;
#pragma unroll
    for (int j = 0; j < 8; j++) {
        int colb = 8 * j + 2 * (lid & 3);
        *(uint32_t*)(Ohi + row0 + colb) = cvt_h2(o[j][0] * inv0, o[j][1] * inv0);
        *(uint32_t*)(Ohi + row1 + colb) = cvt_h2(o[j][2] * inv1, o[j][3] * inv1);
    }
}

// ---------------- embedding + PE, emits fp32 + hi fp16 ----------------
__global__ void embed_kernel(const int* __restrict__ tok,
                             const float* __restrict__ emb,
                             const float* __restrict__ pos,
                             float* __restrict__ out,
                             __half* __restrict__ ohi) {
    int i = blockIdx.x * blockDim.x + threadIdx.x;
    int d = i & (kD - 1);
    int t = i >> 9;
    int s = t & (kS - 1);
    float v = emb[(size_t)tok[t] * kD + d] + pos[s * kD + d];
    out[i] = v;
    ohi[i] = __float2half_rn(v);
}

// ---------------- x = LayerNorm(x + a), emits fp32 + hi fp16 ---------------
__global__ __launch_bounds__(128)
void add_ln_kernel(float* __restrict__ x, const float* __restrict__ a,
                   const float* __restrict__ g, const float* __restrict__ bet,
                   __half* __restrict__ xhi) {
    const int r = blockIdx.x;
    const int tid = threadIdx.x;
    __shared__ float red[4];

    float v[4];
#pragma unroll
    for (int i = 0; i < 4; i++) {
        int c = tid + (i << 7);
        size_t idx = (size_t)r * kD + c;
        v[i] = x[idx] + a[idx];
    }

    float s = v[0] + v[1] + v[2] + v[3];
    for (int o = 16; o; o >>= 1) s += __shfl_xor_sync(0xffffffffu, s, o);
    if ((tid & 31) == 0) red[tid >> 5] = s;
    __syncthreads();
    s = red[0] + red[1] + red[2] + red[3];
    __syncthreads();
    const float mu = s * (1.0f / kD);

    float sq = 0.0f;
#pragma unroll
    for (int i = 0; i < 4; i++) { float d = v[i] - mu; sq += d * d; }
    for (int o = 16; o; o >>= 1) sq += __shfl_xor_sync(0xffffffffu, sq, o);
    if ((tid & 31) == 0) red[tid >> 5] = sq;
    __syncthreads();
    sq = red[0] + red[1] + red[2] + red[3];
    const float rstd = rsqrtf(sq * (1.0f / kD) + kEPS);

#pragma unroll
    for (int i = 0; i < 4; i++) {
        int c = tid + (i << 7);
        size_t idx = (size_t)r * kD + c;
        float o = (v[i] - mu) * rstd * g[c] + bet[c];
        x[idx] = o;
        xhi[idx] = __float2half_rn(o);
    }
}

// ---------------- host-side orchestration ----------------------------------
static void hgemm(const __half* ahi, const __half* bhi,
                  const float* bias, float* C, __half* Chi,
                  int M, int N, int K, int ldc, bool relu) {
    const bool f16 = (Chi != nullptr);
    if (N == 512) {
        dim3 grid(N / 128, M / 64);
        if (f16) {
            if (relu) hgemm_kernel<64, true,  true><<<grid, 256, HG_SMEM64>>>(ahi, bhi, bias, C, Chi, M, N, K, ldc);
            else      hgemm_kernel<64, false, true><<<grid, 256, HG_SMEM64>>>(ahi, bhi, bias, C, Chi, M, N, K, ldc);
        } else {
            if (relu) hgemm_kernel<64, true,  false><<<grid, 256, HG_SMEM64>>>(ahi, bhi, bias, C, Chi, M, N, K, ldc);
            else      hgemm_kernel<64, false, false><<<grid, 256, HG_SMEM64>>>(ahi, bhi, bias, C, Chi, M, N, K, ldc);
        }
    } else {
        dim3 grid(N / 128, M / 128);
        if (f16) {
            if (relu) hgemm_kernel<128, true,  true><<<grid, 256, HG_SMEM128>>>(ahi, bhi, bias, C, Chi, M, N, K, ldc);
            else      hgemm_kernel<128, false, true><<<grid, 256, HG_SMEM128>>>(ahi, bhi, bias, C, Chi, M, N, K, ldc);
        } else {
            if (relu) hgemm_kernel<128, true,  false><<<grid, 256, HG_SMEM128>>>(ahi, bhi, bias, C, Chi, M, N, K, ldc);
            else      hgemm_kernel<128, false, false><<<grid, 256, HG_SMEM128>>>(ahi, bhi, bias, C, Chi, M, N, K, ldc);
        }
    }
}

extern "C" void kernel_launch(void* const* d_in, const int* in_sizes, int n_in,
                              void* d_out, int out_size) {
    const int*   src     = (const int*)d_in[0];
    const int*   tgt     = (const int*)d_in[1];
    const float* enc_emb = (const float*)d_in[2];
    const float* dec_emb = (const float*)d_in[3];
    const float* pos     = (const float*)d_in[4];
    const float* enc_aw  = (const float*)d_in[5];
    const float* enc_ab  = (const float*)d_in[6];
    const float* enc_w1  = (const float*)d_in[7];
    const float* enc_b1  = (const float*)d_in[8];
    const float* enc_w2  = (const float*)d_in[9];
    const float* enc_b2  = (const float*)d_in[10];
    const float* enc_lng = (const float*)d_in[11];
    const float* enc_lnb = (const float*)d_in[12];
    const float* dec_aw  = (const float*)d_in[13];
    const float* dec_ab  = (const float*)d_in[14];
    const float* dec_w1  = (const float*)d_in[15];
    const float* dec_b1  = (const float*)d_in[16];
    const float* dec_w2  = (const float*)d_in[17];
    const float* dec_b2  = (const float*)d_in[18];
    const float* dec_lng = (const float*)d_in[19];
    const float* dec_lnb = (const float*)d_in[20];
    const float* fc_w    = (const float*)d_in[21];
    const float* fc_b    = (const float*)d_in[22];

    float *x, *y, *t;
    __half *whi, *xhi, *yhi, *qhi, *chi, *fhi;
    cudaGetSymbolAddress((void**)&x,   g_x);
    cudaGetSymbolAddress((void**)&y,   g_y);
    cudaGetSymbolAddress((void**)&t,   g_t);
    cudaGetSymbolAddress((void**)&whi, g_whi);
    cudaGetSymbolAddress((void**)&xhi, g_xhi);
    cudaGetSymbolAddress((void**)&yhi, g_yhi);
    cudaGetSymbolAddress((void**)&qhi, g_qhi);
    cudaGetSymbolAddress((void**)&chi, g_chi);
    cudaGetSymbolAddress((void**)&fhi, g_fhi);

    cudaFuncSetAttribute(hgemm_kernel<128, false, false>, cudaFuncAttributeMaxDynamicSharedMemorySize, HG_SMEM128);
    cudaFuncSetAttribute(hgemm_kernel<128, true,  false>, cudaFuncAttributeMaxDynamicSharedMemorySize, HG_SMEM128);
    cudaFuncSetAttribute(hgemm_kernel<128, false, true>,  cudaFuncAttributeMaxDynamicSharedMemorySize, HG_SMEM128);
    cudaFuncSetAttribute(hgemm_kernel<128, true,  true>,  cudaFuncAttributeMaxDynamicSharedMemorySize, HG_SMEM128);
    cudaFuncSetAttribute(hgemm_kernel<64, false, false>,  cudaFuncAttributeMaxDynamicSharedMemorySize, HG_SMEM64);
    cudaFuncSetAttribute(hgemm_kernel<64, true,  false>,  cudaFuncAttributeMaxDynamicSharedMemorySize, HG_SMEM64);
    cudaFuncSetAttribute(hgemm_kernel<64, false, true>,   cudaFuncAttributeMaxDynamicSharedMemorySize, HG_SMEM64);
    cudaFuncSetAttribute(hgemm_kernel<64, true,  true>,   cudaFuncAttributeMaxDynamicSharedMemorySize, HG_SMEM64);
    cudaFuncSetAttribute(flash_kernel, cudaFuncAttributeMaxDynamicSharedMemorySize, FA_SMEM);

    const int embBlocks = (kNT * kD) / 256;

    // keep first QKV hgemm at MY launch index 3 (ncu -s 5 alignment)
    wconv_kernel<<<dim3(16, 16, 24), 256>>>(enc_aw, whi + OFF_EA, kD, kD);
    embed_kernel<<<embBlocks, 256>>>(src, enc_emb, pos, x, xhi);
    wconv_kernel<<<dim3(64, 16, 6),  256>>>(enc_w1, whi + OFF_EW1, kD, kF);
    hgemm(xhi, whi + OFF_EA, enc_ab, nullptr, qhi, kNT, 3 * kD, kD, 3 * kD, false);
    wconv_kernel<<<dim3(16, 64, 6),  256>>>(enc_w2, whi + OFF_EW2, kF, kD);

    // ---------------- encoder ----------------
    for (int l = 0; l < kL; l++) {
        const __half* wh = whi + OFF_EA + (size_t)l * 4 * DD;
        const float* Wb = enc_ab + (size_t)l * 4 * kD;
        if (l > 0)
            hgemm(xhi, wh, Wb, nullptr, qhi, kNT, 3 * kD, kD, 3 * kD, false);
        flash_kernel<<<dim3(kS / 64, kB * kH), 128, FA_SMEM>>>(qhi, chi, nullptr, src, 0);
        hgemm(chi, wh + 3 * DD, Wb + 3 * kD, t, nullptr, kNT, kD, kD, kD, false);
        add_ln_kernel<<<kNT, 128>>>(x, t, enc_lng + (size_t)(l * 2 + 0) * kD,
                                    enc_lnb + (size_t)(l * 2 + 0) * kD, xhi);
        hgemm(xhi, whi + OFF_EW1 + (size_t)l * DF, enc_b1 + (size_t)l * kF,
              nullptr, fhi, kNT, kF, kD, kF, true);
        hgemm(fhi, whi + OFF_EW2 + (size_t)l * DF, enc_b2 + (size_t)l * kD,
              t, nullptr, kNT, kD, kF, kD, false);
        add_ln_kernel<<<kNT, 128>>>(x, t, enc_lng + (size_t)(l * 2 + 1) * kD,
                                    enc_lnb + (size_t)(l * 2 + 1) * kD, xhi);
    }
    // xhi holds enc_out (decoder never overwrites)

    wconv_kernel<<<dim3(16, 16, 48), 256>>>(dec_aw, whi + OFF_DA, kD, kD);
    wconv_kernel<<<dim3(64, 16, 6), 256>>>(dec_w1, whi + OFF_DW1, kD, kF);
    wconv_kernel<<<dim3(16, 64, 6), 256>>>(dec_w2, whi + OFF_DW2, kF, kD);
    wconv_kernel<<<dim3(1000, 16, 1), 256>>>(fc_w, whi + OFF_FC, kD, kV);
    embed_kernel<<<embBlocks, 256>>>(tgt, dec_emb, pos, y, yhi);

    // ---------------- decoder ----------------
    for (int l = 0; l < kL; l++) {
        const __half* wh = whi + OFF_DA + (size_t)l * 8 * DD;
        const float* Wb = dec_ab + (size_t)l * 8 * kD;
        // self-attention
        hgemm(yhi, wh, Wb, nullptr, qhi, kNT, 3 * kD, kD, 3 * kD, false);
        flash_kernel<<<dim3(kS / 64, kB * kH), 128, FA_SMEM>>>(qhi, chi, tgt, tgt, 1);
        hgemm(chi, wh + 3 * DD, Wb + 3 * kD, t, nullptr, kNT, kD, kD, kD, false);
        add_ln_kernel<<<kNT, 128>>>(y, t, dec_lng + (size_t)(l * 3 + 0) * kD,
                                    dec_lnb + (size_t)(l * 3 + 0) * kD, yhi);
        // cross-attention: Q from y, KV from enc_out (xhi)
        hgemm(yhi, wh + 4 * DD, Wb + 4 * kD, nullptr, qhi, kNT, kD, kD, 3 * kD, false);
        hgemm(xhi, wh + 5 * DD, Wb + 5 * kD, nullptr, qhi + kD,
              kNT, 2 * kD, kD, 3 * kD, false);
        flash_kernel<<<dim3(kS / 64, kB * kH), 128, FA_SMEM>>>(qhi, chi, nullptr, src, 0);
        hgemm(chi, wh + 7 * DD, Wb + 7 * kD, t, nullptr, kNT, kD, kD, kD, false);
        add_ln_kernel<<<kNT, 128>>>(y, t, dec_lng + (size_t)(l * 3 + 1) * kD,
                                    dec_lnb + (size_t)(l * 3 + 1) * kD, yhi);
        // FFN
        hgemm(yhi, whi + OFF_DW1 + (size_t)l * DF, dec_b1 + (size_t)l * kF,
              nullptr, fhi, kNT, kF, kD, kF, true);
        hgemm(fhi, whi + OFF_DW2 + (size_t)l * DF, dec_b2 + (size_t)l * kD,
              t, nullptr, kNT, kD, kF, kD, false);
        add_ln_kernel<<<kNT, 128>>>(y, t, dec_lng + (size_t)(l * 3 + 2) * kD,
                                    dec_lnb + (size_t)(l * 3 + 2) * kD, yhi);
    }

    // ---------------- final projection to vocab ----------------
    hgemm(yhi, whi + OFF_FC, fc_b, (float*)d_out, nullptr,
          kNT, kV, kD, kV, false);
}